// round 16
// baseline (speedup 1.0000x reference)
#include <cuda_runtime.h>
#include <cuda_fp16.h>
#include <cstdint>

#define TT 8
#define HH 64
#define WWD 64
#define HWX 4096
#define PLANE 32768
#define KTAP 27

// -------- device scratch --------
__device__ __half g_xh[64*PLANE];        // x fp16, [pos][c]
__device__ __half g_y1h[64*PLANE];       // lrelu(conv1) fp16, [pos][c]
__device__ __half g_W1h[KTAP*64*64];     // [tap][o][c]
__device__ __half g_Woffh[KTAP*64*64];
__device__ __half g_Wdh[KTAP*64*64];
__device__ __half g_Wrh[64*64];          // [o][c]

__device__ __forceinline__ uint32_t smem_u32(const void* p){
    uint32_t a;
    asm("{ .reg .u64 t; cvta.to.shared.u64 t, %1; cvt.u32.u64 %0, t; }"
        : "=r"(a) : "l"(p));
    return a;
}
__device__ __forceinline__ void ldsm4(uint32_t& r0,uint32_t& r1,uint32_t& r2,uint32_t& r3, uint32_t addr){
    asm volatile("ldmatrix.sync.aligned.m8n8.x4.shared.b16 {%0,%1,%2,%3}, [%4];"
        : "=r"(r0),"=r"(r1),"=r"(r2),"=r"(r3) : "r"(addr));
}
__device__ __forceinline__ void mma16816(float* d, uint32_t a0,uint32_t a1,uint32_t a2,uint32_t a3,
                                         uint32_t b0,uint32_t b1){
    asm volatile("mma.sync.aligned.m16n8k16.row.col.f32.f16.f16.f32 "
        "{%0,%1,%2,%3},{%4,%5,%6,%7},{%8,%9},{%0,%1,%2,%3};"
        : "+f"(d[0]),"+f"(d[1]),"+f"(d[2]),"+f"(d[3])
        : "r"(a0),"r"(a1),"r"(a2),"r"(a3),"r"(b0),"r"(b1));
}

// ---- conv gemm: full K=64 tap, A straight from input window, B from slot ----
__device__ __forceinline__ void gemm_conv(uint32_t WinB, int woff, uint32_t Bb, int n0,
                                          int lane, float acc[8][4]){
    int g = lane>>3, r = lane&7;
    #pragma unroll
    for (int st=0; st<4; st++){
        uint32_t a[2][4], b[2][4];
        #pragma unroll
        for (int mi=0;mi<2;mi++){
            int rowA = woff + mi*16 + (g&1)*8 + r;
            int segA = st*2 + (g>>1);
            ldsm4(a[mi][0],a[mi][1],a[mi][2],a[mi][3],
                  WinB + rowA*128 + ((segA ^ (rowA&7))<<4));
        }
        #pragma unroll
        for (int ni=0;ni<2;ni++){
            int rowB = n0 + ni*16 + (g>>1)*8 + r;
            int segB = st*2 + (g&1);
            ldsm4(b[ni][0],b[ni][1],b[ni][2],b[ni][3],
                  Bb + rowB*128 + ((segB ^ (rowB&7))<<4));
        }
        #pragma unroll
        for (int mi=0;mi<2;mi++)
        #pragma unroll
        for (int ni=0;ni<2;ni++){
            mma16816(acc[mi*4+ni*2],   a[mi][0],a[mi][1],a[mi][2],a[mi][3], b[ni][0],b[ni][1]);
            mma16816(acc[mi*4+ni*2+1], a[mi][0],a[mi][1],a[mi][2],a[mi][3], b[ni][2],b[ni][3]);
        }
    }
}

// ---- deform gemm half-chunk (2 of 4 stages), both tiles staged ----
template<int ST0>
__device__ __forceinline__ void gemm_half(uint32_t Ab, uint32_t Bb, int m0, int n0,
                                          int lane, float acc[8][4]){
    int g = lane>>3, r = lane&7;
    #pragma unroll
    for (int s=0;s<2;s++){
        int st = ST0 + s;
        uint32_t a[2][4], b[2][4];
        #pragma unroll
        for (int mi=0;mi<2;mi++){
            int rowA = m0 + mi*16 + (g&1)*8 + r;
            int segA = st*2 + (g>>1);
            ldsm4(a[mi][0],a[mi][1],a[mi][2],a[mi][3],
                  Ab + rowA*128 + ((segA ^ (rowA&7))<<4));
        }
        #pragma unroll
        for (int ni=0;ni<2;ni++){
            int rowB = n0 + ni*16 + (g>>1)*8 + r;
            int segB = st*2 + (g&1);
            ldsm4(b[ni][0],b[ni][1],b[ni][2],b[ni][3],
                  Bb + rowB*128 + ((segB ^ (rowB&7))<<4));
        }
        #pragma unroll
        for (int mi=0;mi<2;mi++)
        #pragma unroll
        for (int ni=0;ni<2;ni++){
            mma16816(acc[mi*4+ni*2],   a[mi][0],a[mi][1],a[mi][2],a[mi][3], b[ni][0],b[ni][1]);
            mma16816(acc[mi*4+ni*2+1], a[mi][0],a[mi][1],a[mi][2],a[mi][3], b[ni][2],b[ni][3]);
        }
    }
}

// half2 bilinear combine: 4 taps x 8 channels, all fp16
__device__ __forceinline__ uint4 bilinH(const uint4* P, uint2 wpack){
    __half2 w01 = *(__half2*)&wpack.x;
    __half2 w23 = *(__half2*)&wpack.y;
    __half2 w00b = __low2half2(w01), w01b = __high2half2(w01);
    __half2 w10b = __low2half2(w23), w11b = __high2half2(w23);
    const uint32_t* p0 = (const uint32_t*)&P[0];
    const uint32_t* p1 = (const uint32_t*)&P[1];
    const uint32_t* p2 = (const uint32_t*)&P[2];
    const uint32_t* p3 = (const uint32_t*)&P[3];
    uint4 r;
    uint32_t* ro = (uint32_t*)&r;
    #pragma unroll
    for (int k=0;k<4;k++){
        __half2 v = __hmul2(*(const __half2*)&p0[k], w00b);
        v = __hfma2(*(const __half2*)&p1[k], w01b, v);
        v = __hfma2(*(const __half2*)&p2[k], w10b, v);
        v = __hfma2(*(const __half2*)&p3[k], w11b, v);
        ro[k] = *(uint32_t*)&v;
    }
    return r;
}

// -------- prep: coalesced weight transpose + x transpose --------
// blocks [0,24): weight tensors (8 o-rows each); 24: Wr; [25,281): x transpose
#define SMEM_PREP 55296
__global__ void prep_all(const float* __restrict__ W1, const float* __restrict__ Woff,
                         const float* __restrict__ Wd, const float* __restrict__ Wr,
                         const float* __restrict__ x){
    extern __shared__ char sm[];
    int tid = threadIdx.x;
    int wb = blockIdx.x;
    if (wb < 24){
        float* smemW = (float*)sm;               // [8][1728]
        int tensor = wb >> 3, o0 = (wb & 7)*8;
        const float* src = (tensor==0) ? W1 : ((tensor==1) ? Wd : Woff);
        __half* dst = (tensor==0) ? g_W1h : ((tensor==1) ? g_Wdh : g_Woffh);
        for (int j = tid; j < 13824; j += 256){
            int o = o0 + j/1728;
            float v = 0.f;
            if (tensor != 2 || o < 54) v = src[o*1728 + (j - (j/1728)*1728)];
            smemW[j] = v;
        }
        __syncthreads();
        for (int j = tid; j < 13824; j += 256){
            int tap = j >> 9;
            int r = j & 511;
            int o = r >> 6, c = r & 63;
            dst[tap*4096 + (o0+o)*64 + c] = __float2half(smemW[o*1728 + c*27 + tap]);
        }
    } else if (wb == 24){
        for (int j = tid; j < 4096; j += 256) g_Wrh[j] = __float2half(Wr[j]);
    } else {
        __half* sT = (__half*)sm;                // [128][72]
        int pos0 = (wb - 25)*128;
        int p = tid & 127, ch0 = tid >> 7;
        #pragma unroll 8
        for (int cc = 0; cc < 32; cc++){
            int c = cc*2 + ch0;
            sT[p*72 + c] = __float2half(x[c*PLANE + pos0 + p]);
        }
        __syncthreads();
        int oc = tid & 7;
        #pragma unroll
        for (int j = 0; j < 4; j++){
            int n = (tid>>3) + j*32;
            uint4 v = *(uint4*)&sT[n*72 + oc*8];
            *(uint4*)&g_xh[(pos0+n)*64 + oc*8] = v;
        }
    }
}

// ==================== conv1: x -> y1 (lrelu), window + 9 B-slots per kt ====================
// smem: misc[0,1024) | WIN@1024 (33792) | B slots @34816 (9*8192=73728) end 108544
#define SMEM_CONV 108544
__global__ void __launch_bounds__(256)
conv0_f16(const float* __restrict__ bias)
{
    extern __shared__ char sm[];
    float* sBias = (float*)sm;
    char* WIN = sm + 1024;
    char* SB  = sm + 34816;
    uint32_t sbase = smem_u32(sm);
    uint32_t WinB = sbase + 1024;
    uint32_t Bb0  = sbase + 34816;

    int tid = threadIdx.x, lane = tid&31, wid = tid>>5;
    int t = blockIdx.x>>5, h0 = (blockIdx.x&31)<<1;
    if (tid < 64) sBias[tid] = bias[tid];

    int o_w = tid>>2, part = tid&3, s0w = part*2;
    int m0 = (wid&3)*32, n0 = (wid>>2)*32;
    float acc[8][4];
    #pragma unroll
    for (int i=0;i<8;i++){ acc[i][0]=0.f; acc[i][1]=0.f; acc[i][2]=0.f; acc[i][3]=0.f; }

    int whh = (m0>>6)*66 + (m0&63);

    for (int kt=0; kt<3; kt++){
        int t_in = t-1+kt;
        bool tok = (unsigned)t_in < TT;
        if (kt) __syncthreads();
        for (int e = tid; e < 2112; e += 256){
            int pos = e >> 3, seg = e & 7;
            int hr = pos/66, wc = pos - hr*66;
            int h_in = h0 + hr - 1, w_in = wc - 1;
            uint4 v = make_uint4(0,0,0,0);
            if (tok && (unsigned)h_in < HH && (unsigned)w_in < WWD)
                v = *(const uint4*)&g_xh[(t_in*HWX + h_in*WWD + w_in)*64 + seg*8];
            *(uint4*)(WIN + pos*128 + ((seg ^ (pos&7))<<4)) = v;
        }
        #pragma unroll
        for (int j=0;j<9;j++){
            const uint4* sp = (const uint4*)(g_W1h + (kt*9+j)*4096 + o_w*64 + part*16);
            uint4 v0 = sp[0], v1 = sp[1];
            char* SBj = SB + j*8192;
            *(uint4*)(SBj + o_w*128 + ((s0w ^ (o_w&7))<<4)) = v0;
            *(uint4*)(SBj + o_w*128 + (((s0w+1)^(o_w&7))<<4)) = v1;
        }
        __syncthreads();
        #pragma unroll
        for (int j=0;j<9;j++){
            int kh = j/3, kw = j - kh*3;
            gemm_conv(WinB, whh + kh*66 + kw, Bb0 + j*8192, n0, lane, acc);
        }
    }
    __syncthreads();

    int q = lane>>2, c2 = (lane&3)<<1;
    int base = t*HWX + h0*WWD;
    int oc = tid&7;
    uint32_t* sOutH2 = (uint32_t*)(sm + 1024);  // [pos][36] half2
    #pragma unroll
    for (int t8=0;t8<8;t8++){
        int mi=t8>>2, ni=(t8>>1)&1, hn=t8&1;
        int o = n0 + ni*16 + hn*8 + c2;
        int r0 = m0 + mi*16 + q;
        float b0v = sBias[o], b1v = sBias[o+1];
        float v0 = acc[t8][0]+b0v, v1 = acc[t8][1]+b1v;
        float v2 = acc[t8][2]+b0v, v3 = acc[t8][3]+b1v;
        v0 = v0>=0.f?v0:0.01f*v0; v1 = v1>=0.f?v1:0.01f*v1;
        v2 = v2>=0.f?v2:0.01f*v2; v3 = v3>=0.f?v3:0.01f*v3;
        __half2 h01 = __floats2half2_rn(v0,v1);
        __half2 h23 = __floats2half2_rn(v2,v3);
        sOutH2[r0*36     + (o>>1)] = *(uint32_t*)&h01;
        sOutH2[(r0+8)*36 + (o>>1)] = *(uint32_t*)&h23;
    }
    __syncthreads();
    __half* sOutH = (__half*)(sm + 1024);
    #pragma unroll
    for (int jj=0;jj<4;jj++){
        int n = (tid>>3) + jj*32;
        uint4 v = *(uint4*)&sOutH[n*72 + oc*8];
        *(uint4*)&g_y1h[(base+n)*64 + oc*8] = v;
    }
}

// ==================== FUSED: offset conv -> tap table -> deform + residual + lrelu ====================
// conv phase:  misc[0,1024) | WIN@1024 (33792) | B slots @34816 (73728) end 108544
// transition:  sOut fp32 [o][132] @1024 | sOff@50176 (27648) | sWt@77824 (27648)
// deform phase: SA0@1024 SA1@17408 SB0@33792 SB1@41984 | sOff/sWt persist
#define SMEM_FUSED 108544

__device__ __forceinline__ void dledg(int tap, int tid, const uint2* sOff, const uint2* sWt,
                                      uint4 P[2][4], uint2 Wp[2], int j0){
    int oc = tid&7;
    #pragma unroll
    for (int jj=0;jj<2;jj++){
        int n = (tid>>3) + (j0+jj)*32;
        int te = tap*128 + n;
        uint2 of = sOff[te];
        Wp[jj] = sWt[te];
        P[jj][0] = *(const uint4*)&g_y1h[(of.x & 0xFFFF)*64 + oc*8];
        P[jj][1] = *(const uint4*)&g_y1h[(of.x >> 16)*64 + oc*8];
        P[jj][2] = *(const uint4*)&g_y1h[(of.y & 0xFFFF)*64 + oc*8];
        P[jj][3] = *(const uint4*)&g_y1h[(of.y >> 16)*64 + oc*8];
    }
}
__device__ __forceinline__ void rledg(int tid, int base_p, uint4 P[2][4], uint2 Wp[2], int j0){
    int oc = tid&7;
    __half2 one0 = __floats2half2_rn(1.f, 0.f);
    __half2 zero = __floats2half2_rn(0.f, 0.f);
    uint2 w; w.x = *(uint32_t*)&one0; w.y = *(uint32_t*)&zero;
    #pragma unroll
    for (int jj=0;jj<2;jj++){
        int n = (tid>>3) + (j0+jj)*32;
        P[jj][0] = *(const uint4*)&g_xh[(base_p+n)*64 + oc*8];
        P[jj][1] = make_uint4(0,0,0,0);
        P[jj][2] = make_uint4(0,0,0,0);
        P[jj][3] = make_uint4(0,0,0,0);
        Wp[jj] = w;
    }
}
__device__ __forceinline__ void dlsts(char* SA, int tid, uint4 P[2][4], uint2 Wp[2], int j0){
    int oc = tid&7;
    #pragma unroll
    for (int jj=0;jj<2;jj++){
        int n = (tid>>3) + (j0+jj)*32;
        uint4 r = bilinH(P[jj], Wp[jj]);
        *(uint4*)(SA + n*128 + ((oc ^ (n&7))<<4)) = r;
    }
}

__global__ void __launch_bounds__(256, 2)
offdef_f16(const float* __restrict__ boff, const float* __restrict__ bd,
           const float* __restrict__ br, float* __restrict__ out)
{
    extern __shared__ char sm[];
    float* sBias = (float*)sm;
    float* sBd = (float*)(sm + 256);
    float* sBr = (float*)(sm + 512);
    char* WIN = sm + 1024;
    char* SBc = sm + 34816;
    char* SA0 = sm + 1024;
    char* SA1 = sm + 17408;
    char* SB0 = sm + 33792;
    char* SB1 = sm + 41984;
    uint2* sOff = (uint2*)(sm + 50176);
    uint2* sWt  = (uint2*)(sm + 77824);
    uint32_t sbase = smem_u32(sm);
    uint32_t WinB = sbase + 1024;
    uint32_t Bb0  = sbase + 34816;

    int tid = threadIdx.x, lane = tid&31, wid = tid>>5;
    int t = blockIdx.x>>5, h0 = (blockIdx.x&31)<<1;
    int base_p = t*HWX + h0*WWD;
    if (tid < 64){
        sBias[tid] = (tid < 54) ? boff[tid] : 0.f;
        sBd[tid] = bd[tid]; sBr[tid] = br[tid];
    }

    int o_w = tid>>2, part = tid&3, s0w = part*2;
    int m0 = (wid&3)*32, n0 = (wid>>2)*32;
    float acc[8][4];
    #pragma unroll
    for (int i=0;i<8;i++){ acc[i][0]=0.f; acc[i][1]=0.f; acc[i][2]=0.f; acc[i][3]=0.f; }

    int whh = (m0>>6)*66 + (m0&63);

    // ---------- phase A: offset conv (y1h -> offsets, 54 ch) ----------
    for (int kt=0; kt<3; kt++){
        int t_in = t-1+kt;
        bool tok = (unsigned)t_in < TT;
        if (kt) __syncthreads();
        for (int e = tid; e < 2112; e += 256){
            int pos = e >> 3, seg = e & 7;
            int hr = pos/66, wc = pos - hr*66;
            int h_in = h0 + hr - 1, w_in = wc - 1;
            uint4 v = make_uint4(0,0,0,0);
            if (tok && (unsigned)h_in < HH && (unsigned)w_in < WWD)
                v = *(const uint4*)&g_y1h[(t_in*HWX + h_in*WWD + w_in)*64 + seg*8];
            *(uint4*)(WIN + pos*128 + ((seg ^ (pos&7))<<4)) = v;
        }
        #pragma unroll
        for (int j=0;j<9;j++){
            const uint4* sp = (const uint4*)(g_Woffh + (kt*9+j)*4096 + o_w*64 + part*16);
            uint4 v0 = sp[0], v1 = sp[1];
            char* SBj = SBc + j*8192;
            *(uint4*)(SBj + o_w*128 + ((s0w ^ (o_w&7))<<4)) = v0;
            *(uint4*)(SBj + o_w*128 + (((s0w+1)^(o_w&7))<<4)) = v1;
        }
        __syncthreads();
        #pragma unroll
        for (int j=0;j<9;j++){
            int kh = j/3, kw = j - kh*3;
            gemm_conv(WinB, whh + kh*66 + kw, Bb0 + j*8192, n0, lane, acc);
        }
    }
    __syncthreads();

    int q = lane>>2, c2 = (lane&3)<<1;
    // ---------- transition: offsets -> smem fp32 -> tap table ----------
    {
        float* sOut = (float*)(sm + 1024);   // [o][132]
        #pragma unroll
        for (int t8=0;t8<8;t8++){
            int mi=t8>>2, ni=(t8>>1)&1, hn=t8&1;
            int o = n0 + ni*16 + hn*8 + c2;
            int nn = m0 + mi*16 + q;
            float b0v = sBias[o], b1v = sBias[o+1];
            sOut[o*132+nn]       = acc[t8][0]+b0v;
            sOut[(o+1)*132+nn]   = acc[t8][1]+b1v;
            sOut[o*132+nn+8]     = acc[t8][2]+b0v;
            sOut[(o+1)*132+nn+8] = acc[t8][3]+b1v;
        }
        __syncthreads();
        for (int e = tid; e < KTAP*128; e += 256){
            int tap = e>>7, n = e&127;
            float dh = sOut[(2*tap)*132 + n];
            float dw = sOut[(2*tap+1)*132 + n];
            int hh = n>>6, w = n&63;
            int h = h0 + hh;
            int kt = tap/9, rr = tap-kt*9, kh = rr/3, kw = rr-kh*3;
            int t_in = t-1+kt;
            bool t_ok = (unsigned)t_in < TT;
            int t_c = min(max(t_in,0),TT-1);
            float h_s = (float)(h-1+kh)+dh, w_s = (float)(w-1+kw)+dw;
            float h0f = floorf(h_s), w0f = floorf(w_s);
            float fh = h_s-h0f, fw = w_s-w0f;
            int hb = (int)h0f, wb = (int)w0f;
            float wgt[4];
            unsigned short ofs[4];
            int tb = t_c*HWX;
            #pragma unroll
            for (int qq = 0; qq < 4; qq++){
                int ih = hb + (qq>>1), iw = wb + (qq&1);
                bool ok = t_ok && ((unsigned)ih < HH) && ((unsigned)iw < WWD);
                int ihc = min(max(ih,0),HH-1), iwc = min(max(iw,0),WWD-1);
                float whv = (qq>>1) ? fh : 1.f - fh;
                float wvv = (qq&1)  ? fw : 1.f - fw;
                wgt[qq] = ok ? whv*wvv : 0.f;
                ofs[qq] = (unsigned short)(tb + ihc*WWD + iwc);
            }
            __half2 w01 = __floats2half2_rn(wgt[0], wgt[1]);
            __half2 w23 = __floats2half2_rn(wgt[2], wgt[3]);
            sOff[e] = make_uint2((uint32_t)ofs[0] | ((uint32_t)ofs[1]<<16),
                                 (uint32_t)ofs[2] | ((uint32_t)ofs[3]<<16));
            uint2 wp; wp.x = *(uint32_t*)&w01; wp.y = *(uint32_t*)&w23;
            sWt[e] = wp;
        }
    }
    __syncthreads();

    // ---------- phase B: deformable GEMM + residual ----------
    #pragma unroll
    for (int i=0;i<8;i++){ acc[i][0]=0.f; acc[i][1]=0.f; acc[i][2]=0.f; acc[i][3]=0.f; }

    {
        uint4 P[2][4]; uint2 Wp[2];
        dledg(0, tid, sOff, sWt, P, Wp, 0); dlsts(SA0, tid, P, Wp, 0);
        dledg(0, tid, sOff, sWt, P, Wp, 2); dlsts(SA0, tid, P, Wp, 2);
        const uint4* sp = (const uint4*)(g_Wdh + o_w*64 + part*16);
        uint4 wv0 = sp[0], wv1 = sp[1];
        *(uint4*)(SB0 + o_w*128 + ((s0w ^ (o_w&7))<<4)) = wv0;
        *(uint4*)(SB0 + o_w*128 + (((s0w+1)^(o_w&7))<<4)) = wv1;
    }
    __syncthreads();

    for (int it = 0; it < 28; it++){
        int p = it & 1;
        uint32_t Ab = sbase + (p ? 17408 : 1024);
        uint32_t Bb = sbase + (p ? 41984 : 33792);
        char* SAn = p ? SA0 : SA1;
        char* SBn = p ? SB0 : SB1;
        int nxt = it + 1;
        bool more = nxt < 28;

        uint4 P[2][4]; uint2 Wp[2];
        uint4 wv0, wv1;
        if (more){
            if (nxt < 27) dledg(nxt, tid, sOff, sWt, P, Wp, 0);
            else          rledg(tid, base_p, P, Wp, 0);
            const __half* Wsrc = (nxt < 27) ? (g_Wdh + nxt*4096) : g_Wrh;
            const uint4* sp = (const uint4*)(Wsrc + o_w*64 + part*16);
            wv0 = sp[0]; wv1 = sp[1];
        }
        gemm_half<0>(Ab, Bb, m0, n0, lane, acc);
        if (more){
            dlsts(SAn, tid, P, Wp, 0);
            if (nxt < 27) dledg(nxt, tid, sOff, sWt, P, Wp, 2);
            else          rledg(tid, base_p, P, Wp, 2);
        }
        gemm_half<2>(Ab, Bb, m0, n0, lane, acc);
        if (more){
            dlsts(SAn, tid, P, Wp, 2);
            *(uint4*)(SBn + o_w*128 + ((s0w ^ (o_w&7))<<4)) = wv0;
            *(uint4*)(SBn + o_w*128 + (((s0w+1)^(o_w&7))<<4)) = wv1;
        }
        if (it == 26){
            #pragma unroll
            for (int t8=0;t8<8;t8++){
                int ni=(t8>>1)&1, hn=t8&1;
                int o = n0 + ni*16 + hn*8 + c2;
                float b0v = sBd[o], b1v = sBd[o+1];
                float v;
                v = acc[t8][0]+b0v; acc[t8][0] = v>=0.f?v:0.01f*v;
                v = acc[t8][1]+b1v; acc[t8][1] = v>=0.f?v:0.01f*v;
                v = acc[t8][2]+b0v; acc[t8][2] = v>=0.f?v:0.01f*v;
                v = acc[t8][3]+b1v; acc[t8][3] = v>=0.f?v:0.01f*v;
            }
        }
        __syncthreads();
    }

    float* sOut = (float*)(sm + 1024);  // [o][132]
    #pragma unroll
    for (int t8=0;t8<8;t8++){
        int mi=t8>>2, ni=(t8>>1)&1, hn=t8&1;
        int o = n0 + ni*16 + hn*8 + c2;
        int nn = m0 + mi*16 + q;
        float b0v = sBr[o], b1v = sBr[o+1];
        sOut[o*132+nn]       = acc[t8][0]+b0v;
        sOut[(o+1)*132+nn]   = acc[t8][1]+b1v;
        sOut[o*132+nn+8]     = acc[t8][2]+b0v;
        sOut[(o+1)*132+nn+8] = acc[t8][3]+b1v;
    }
    __syncthreads();
    int n4 = (tid&31)*4;
    #pragma unroll
    for (int i=0;i<8;i++){
        int o = (tid>>5) + i*8;
        float4 v = *(float4*)&sOut[o*132+n4];
        *(float4*)&out[o*PLANE + base_p + n4] = v;
    }
}

// -------- launch --------
extern "C" void kernel_launch(void* const* d_in, const int* in_sizes, int n_in,
                              void* d_out, int out_size) {
    (void)in_sizes; (void)n_in; (void)out_size;
    const float* x    = (const float*)d_in[0];
    const float* W1   = (const float*)d_in[1];
    const float* b1   = (const float*)d_in[2];
    const float* Woff = (const float*)d_in[3];
    const float* boff = (const float*)d_in[4];
    const float* Wd   = (const float*)d_in[5];
    const float* bd   = (const float*)d_in[6];
    const float* Wr   = (const float*)d_in[7];
    const float* br   = (const float*)d_in[8];
    float* out = (float*)d_out;

    cudaFuncSetAttribute(prep_all,   cudaFuncAttributeMaxDynamicSharedMemorySize, SMEM_PREP);
    cudaFuncSetAttribute(conv0_f16,  cudaFuncAttributeMaxDynamicSharedMemorySize, SMEM_CONV);
    cudaFuncSetAttribute(offdef_f16, cudaFuncAttributeMaxDynamicSharedMemorySize, SMEM_FUSED);

    prep_all<<<281, 256, SMEM_PREP>>>(W1, Woff, Wd, Wr, x);
    conv0_f16<<<256, 256, SMEM_CONV>>>(b1);
    offdef_f16<<<256, 256, SMEM_FUSED>>>(boff, bd, br, out);
}

// round 17
// speedup vs baseline: 1.0123x; 1.0123x over previous
#include <cuda_runtime.h>
#include <cuda_fp16.h>
#include <cstdint>

#define TT 8
#define HH 64
#define WWD 64
#define HWX 4096
#define PLANE 32768
#define KTAP 27

// -------- device scratch --------
__device__ __half g_xh[64*PLANE];        // x fp16, [pos][c]
__device__ __half g_y1h[64*PLANE];       // lrelu(conv1) fp16, [pos][c]
__device__ __half g_W1h[KTAP*64*64];     // [tap][o][c]
__device__ __half g_Woffh[KTAP*64*64];
__device__ __half g_Wdh[KTAP*64*64];
__device__ __half g_Wrh[64*64];          // [o][c]

__device__ __forceinline__ uint32_t smem_u32(const void* p){
    uint32_t a;
    asm("{ .reg .u64 t; cvta.to.shared.u64 t, %1; cvt.u32.u64 %0, t; }"
        : "=r"(a) : "l"(p));
    return a;
}
__device__ __forceinline__ void ldsm4(uint32_t& r0,uint32_t& r1,uint32_t& r2,uint32_t& r3, uint32_t addr){
    asm volatile("ldmatrix.sync.aligned.m8n8.x4.shared.b16 {%0,%1,%2,%3}, [%4];"
        : "=r"(r0),"=r"(r1),"=r"(r2),"=r"(r3) : "r"(addr));
}
__device__ __forceinline__ void mma16816(float* d, uint32_t a0,uint32_t a1,uint32_t a2,uint32_t a3,
                                         uint32_t b0,uint32_t b1){
    asm volatile("mma.sync.aligned.m16n8k16.row.col.f32.f16.f16.f32 "
        "{%0,%1,%2,%3},{%4,%5,%6,%7},{%8,%9},{%0,%1,%2,%3};"
        : "+f"(d[0]),"+f"(d[1]),"+f"(d[2]),"+f"(d[3])
        : "r"(a0),"r"(a1),"r"(a2),"r"(a3),"r"(b0),"r"(b1));
}

// ---- conv gemm: full K=64 tap, A straight from input window, B from slot ----
__device__ __forceinline__ void gemm_conv(uint32_t WinB, int woff, uint32_t Bb, int n0,
                                          int lane, float acc[8][4]){
    int g = lane>>3, r = lane&7;
    #pragma unroll
    for (int st=0; st<4; st++){
        uint32_t a[2][4], b[2][4];
        #pragma unroll
        for (int mi=0;mi<2;mi++){
            int rowA = woff + mi*16 + (g&1)*8 + r;
            int segA = st*2 + (g>>1);
            ldsm4(a[mi][0],a[mi][1],a[mi][2],a[mi][3],
                  WinB + rowA*128 + ((segA ^ (rowA&7))<<4));
        }
        #pragma unroll
        for (int ni=0;ni<2;ni++){
            int rowB = n0 + ni*16 + (g>>1)*8 + r;
            int segB = st*2 + (g&1);
            ldsm4(b[ni][0],b[ni][1],b[ni][2],b[ni][3],
                  Bb + rowB*128 + ((segB ^ (rowB&7))<<4));
        }
        #pragma unroll
        for (int mi=0;mi<2;mi++)
        #pragma unroll
        for (int ni=0;ni<2;ni++){
            mma16816(acc[mi*4+ni*2],   a[mi][0],a[mi][1],a[mi][2],a[mi][3], b[ni][0],b[ni][1]);
            mma16816(acc[mi*4+ni*2+1], a[mi][0],a[mi][1],a[mi][2],a[mi][3], b[ni][2],b[ni][3]);
        }
    }
}

// ---- deform gemm half-chunk (2 of 4 stages), both tiles staged ----
template<int ST0>
__device__ __forceinline__ void gemm_half(uint32_t Ab, uint32_t Bb, int m0, int n0,
                                          int lane, float acc[8][4]){
    int g = lane>>3, r = lane&7;
    #pragma unroll
    for (int s=0;s<2;s++){
        int st = ST0 + s;
        uint32_t a[2][4], b[2][4];
        #pragma unroll
        for (int mi=0;mi<2;mi++){
            int rowA = m0 + mi*16 + (g&1)*8 + r;
            int segA = st*2 + (g>>1);
            ldsm4(a[mi][0],a[mi][1],a[mi][2],a[mi][3],
                  Ab + rowA*128 + ((segA ^ (rowA&7))<<4));
        }
        #pragma unroll
        for (int ni=0;ni<2;ni++){
            int rowB = n0 + ni*16 + (g>>1)*8 + r;
            int segB = st*2 + (g&1);
            ldsm4(b[ni][0],b[ni][1],b[ni][2],b[ni][3],
                  Bb + rowB*128 + ((segB ^ (rowB&7))<<4));
        }
        #pragma unroll
        for (int mi=0;mi<2;mi++)
        #pragma unroll
        for (int ni=0;ni<2;ni++){
            mma16816(acc[mi*4+ni*2],   a[mi][0],a[mi][1],a[mi][2],a[mi][3], b[ni][0],b[ni][1]);
            mma16816(acc[mi*4+ni*2+1], a[mi][0],a[mi][1],a[mi][2],a[mi][3], b[ni][2],b[ni][3]);
        }
    }
}

// half2 bilinear combine: 4 taps x 8 channels, all fp16
__device__ __forceinline__ uint4 bilinH(const uint4* P, uint2 wpack){
    __half2 w01 = *(__half2*)&wpack.x;
    __half2 w23 = *(__half2*)&wpack.y;
    __half2 w00b = __low2half2(w01), w01b = __high2half2(w01);
    __half2 w10b = __low2half2(w23), w11b = __high2half2(w23);
    const uint32_t* p0 = (const uint32_t*)&P[0];
    const uint32_t* p1 = (const uint32_t*)&P[1];
    const uint32_t* p2 = (const uint32_t*)&P[2];
    const uint32_t* p3 = (const uint32_t*)&P[3];
    uint4 r;
    uint32_t* ro = (uint32_t*)&r;
    #pragma unroll
    for (int k=0;k<4;k++){
        __half2 v = __hmul2(*(const __half2*)&p0[k], w00b);
        v = __hfma2(*(const __half2*)&p1[k], w01b, v);
        v = __hfma2(*(const __half2*)&p2[k], w10b, v);
        v = __hfma2(*(const __half2*)&p3[k], w11b, v);
        ro[k] = *(uint32_t*)&v;
    }
    return r;
}

// -------- prep (scattered, high-TLP): blocks [0,432) weights; [432,688) x transpose --------
__global__ void prep_all(const float* __restrict__ W1, const float* __restrict__ Woff,
                         const float* __restrict__ Wd, const float* __restrict__ Wr,
                         const float* __restrict__ x){
    __shared__ __half sT[128*72];
    int tid = threadIdx.x;
    if (blockIdx.x < 432){
        int i = blockIdx.x*256 + tid;
        if (i < KTAP*64*64){
            int tap = i>>12, o = (i>>6)&63, c = i&63;
            int src = o*1728 + c*27 + tap;
            g_W1h[i] = __float2half(W1[src]);
            g_Wdh[i] = __float2half(Wd[src]);
            g_Woffh[i] = (o < 54) ? __float2half(Woff[src]) : __half(0.f);
            if (i < 64*64) g_Wrh[i] = __float2half(Wr[i]);
        }
    } else {
        int pos0 = (blockIdx.x - 432)*128;
        int p = tid & 127, ch0 = tid >> 7;
        #pragma unroll 8
        for (int cc = 0; cc < 32; cc++){
            int c = cc*2 + ch0;
            sT[p*72 + c] = __float2half(x[c*PLANE + pos0 + p]);
        }
        __syncthreads();
        int oc = tid & 7;
        #pragma unroll
        for (int j = 0; j < 4; j++){
            int n = (tid>>3) + j*32;
            uint4 v = *(uint4*)&sT[n*72 + oc*8];
            *(uint4*)&g_xh[(pos0+n)*64 + oc*8] = v;
        }
    }
}

// ==================== conv1: x -> y1 (lrelu), window + 9 B-slots per kt ====================
// smem: misc[0,1024) | WIN@1024 (33792) | B slots @34816 (9*8192=73728) end 108544
#define SMEM_CONV 108544
__global__ void __launch_bounds__(256)
conv0_f16(const float* __restrict__ bias)
{
    extern __shared__ char sm[];
    float* sBias = (float*)sm;
    char* WIN = sm + 1024;
    char* SB  = sm + 34816;
    uint32_t sbase = smem_u32(sm);
    uint32_t WinB = sbase + 1024;
    uint32_t Bb0  = sbase + 34816;

    int tid = threadIdx.x, lane = tid&31, wid = tid>>5;
    int t = blockIdx.x>>5, h0 = (blockIdx.x&31)<<1;
    if (tid < 64) sBias[tid] = bias[tid];

    int o_w = tid>>2, part = tid&3, s0w = part*2;
    int m0 = (wid&3)*32, n0 = (wid>>2)*32;
    float acc[8][4];
    #pragma unroll
    for (int i=0;i<8;i++){ acc[i][0]=0.f; acc[i][1]=0.f; acc[i][2]=0.f; acc[i][3]=0.f; }

    int whh = (m0>>6)*66 + (m0&63);

    for (int kt=0; kt<3; kt++){
        int t_in = t-1+kt;
        bool tok = (unsigned)t_in < TT;
        if (kt) __syncthreads();
        for (int e = tid; e < 2112; e += 256){
            int pos = e >> 3, seg = e & 7;
            int hr = pos/66, wc = pos - hr*66;
            int h_in = h0 + hr - 1, w_in = wc - 1;
            uint4 v = make_uint4(0,0,0,0);
            if (tok && (unsigned)h_in < HH && (unsigned)w_in < WWD)
                v = *(const uint4*)&g_xh[(t_in*HWX + h_in*WWD + w_in)*64 + seg*8];
            *(uint4*)(WIN + pos*128 + ((seg ^ (pos&7))<<4)) = v;
        }
        #pragma unroll
        for (int j=0;j<9;j++){
            const uint4* sp = (const uint4*)(g_W1h + (kt*9+j)*4096 + o_w*64 + part*16);
            uint4 v0 = sp[0], v1 = sp[1];
            char* SBj = SB + j*8192;
            *(uint4*)(SBj + o_w*128 + ((s0w ^ (o_w&7))<<4)) = v0;
            *(uint4*)(SBj + o_w*128 + (((s0w+1)^(o_w&7))<<4)) = v1;
        }
        __syncthreads();
        #pragma unroll
        for (int j=0;j<9;j++){
            int kh = j/3, kw = j - kh*3;
            gemm_conv(WinB, whh + kh*66 + kw, Bb0 + j*8192, n0, lane, acc);
        }
    }
    __syncthreads();

    int q = lane>>2, c2 = (lane&3)<<1;
    int base = t*HWX + h0*WWD;
    int oc = tid&7;
    uint32_t* sOutH2 = (uint32_t*)(sm + 1024);  // [pos][36] half2
    #pragma unroll
    for (int t8=0;t8<8;t8++){
        int mi=t8>>2, ni=(t8>>1)&1, hn=t8&1;
        int o = n0 + ni*16 + hn*8 + c2;
        int r0 = m0 + mi*16 + q;
        float b0v = sBias[o], b1v = sBias[o+1];
        float v0 = acc[t8][0]+b0v, v1 = acc[t8][1]+b1v;
        float v2 = acc[t8][2]+b0v, v3 = acc[t8][3]+b1v;
        v0 = v0>=0.f?v0:0.01f*v0; v1 = v1>=0.f?v1:0.01f*v1;
        v2 = v2>=0.f?v2:0.01f*v2; v3 = v3>=0.f?v3:0.01f*v3;
        __half2 h01 = __floats2half2_rn(v0,v1);
        __half2 h23 = __floats2half2_rn(v2,v3);
        sOutH2[r0*36     + (o>>1)] = *(uint32_t*)&h01;
        sOutH2[(r0+8)*36 + (o>>1)] = *(uint32_t*)&h23;
    }
    __syncthreads();
    __half* sOutH = (__half*)(sm + 1024);
    #pragma unroll
    for (int jj=0;jj<4;jj++){
        int n = (tid>>3) + jj*32;
        uint4 v = *(uint4*)&sOutH[n*72 + oc*8];
        *(uint4*)&g_y1h[(base+n)*64 + oc*8] = v;
    }
}

// ==================== FUSED: offset conv -> tap table -> deform + residual + lrelu ====================
#define SMEM_FUSED 108544

__device__ __forceinline__ void dledg(int tap, int tid, const uint2* sOff, const uint2* sWt,
                                      uint4 P[2][4], uint2 Wp[2], int j0){
    int oc = tid&7;
    #pragma unroll
    for (int jj=0;jj<2;jj++){
        int n = (tid>>3) + (j0+jj)*32;
        int te = tap*128 + n;
        uint2 of = sOff[te];
        Wp[jj] = sWt[te];
        P[jj][0] = *(const uint4*)&g_y1h[(of.x & 0xFFFF)*64 + oc*8];
        P[jj][1] = *(const uint4*)&g_y1h[(of.x >> 16)*64 + oc*8];
        P[jj][2] = *(const uint4*)&g_y1h[(of.y & 0xFFFF)*64 + oc*8];
        P[jj][3] = *(const uint4*)&g_y1h[(of.y >> 16)*64 + oc*8];
    }
}
__device__ __forceinline__ void rledg(int tid, int base_p, uint4 P[2][4], uint2 Wp[2], int j0){
    int oc = tid&7;
    __half2 one0 = __floats2half2_rn(1.f, 0.f);
    __half2 zero = __floats2half2_rn(0.f, 0.f);
    uint2 w; w.x = *(uint32_t*)&one0; w.y = *(uint32_t*)&zero;
    #pragma unroll
    for (int jj=0;jj<2;jj++){
        int n = (tid>>3) + (j0+jj)*32;
        P[jj][0] = *(const uint4*)&g_xh[(base_p+n)*64 + oc*8];
        P[jj][1] = make_uint4(0,0,0,0);
        P[jj][2] = make_uint4(0,0,0,0);
        P[jj][3] = make_uint4(0,0,0,0);
        Wp[jj] = w;
    }
}
__device__ __forceinline__ void dlsts(char* SA, int tid, uint4 P[2][4], uint2 Wp[2], int j0){
    int oc = tid&7;
    #pragma unroll
    for (int jj=0;jj<2;jj++){
        int n = (tid>>3) + (j0+jj)*32;
        uint4 r = bilinH(P[jj], Wp[jj]);
        *(uint4*)(SA + n*128 + ((oc ^ (n&7))<<4)) = r;
    }
}

__global__ void __launch_bounds__(256, 2)
offdef_f16(const float* __restrict__ boff, const float* __restrict__ bd,
           const float* __restrict__ br, float* __restrict__ out)
{
    extern __shared__ char sm[];
    float* sBias = (float*)sm;
    float* sBd = (float*)(sm + 256);
    float* sBr = (float*)(sm + 512);
    char* WIN = sm + 1024;
    char* SBc = sm + 34816;
    char* SA0 = sm + 1024;
    char* SA1 = sm + 17408;
    char* SB0 = sm + 33792;
    char* SB1 = sm + 41984;
    uint2* sOff = (uint2*)(sm + 50176);
    uint2* sWt  = (uint2*)(sm + 77824);
    uint32_t sbase = smem_u32(sm);
    uint32_t WinB = sbase + 1024;
    uint32_t Bb0  = sbase + 34816;

    int tid = threadIdx.x, lane = tid&31, wid = tid>>5;
    int t = blockIdx.x>>5, h0 = (blockIdx.x&31)<<1;
    int base_p = t*HWX + h0*WWD;
    if (tid < 64){
        sBias[tid] = (tid < 54) ? boff[tid] : 0.f;
        sBd[tid] = bd[tid]; sBr[tid] = br[tid];
    }

    int o_w = tid>>2, part = tid&3, s0w = part*2;
    int m0 = (wid&3)*32, n0 = (wid>>2)*32;
    float acc[8][4];
    #pragma unroll
    for (int i=0;i<8;i++){ acc[i][0]=0.f; acc[i][1]=0.f; acc[i][2]=0.f; acc[i][3]=0.f; }

    int whh = (m0>>6)*66 + (m0&63);

    // ---------- phase A: offset conv (y1h -> offsets, 54 ch) ----------
    for (int kt=0; kt<3; kt++){
        int t_in = t-1+kt;
        bool tok = (unsigned)t_in < TT;
        if (kt) __syncthreads();
        for (int e = tid; e < 2112; e += 256){
            int pos = e >> 3, seg = e & 7;
            int hr = pos/66, wc = pos - hr*66;
            int h_in = h0 + hr - 1, w_in = wc - 1;
            uint4 v = make_uint4(0,0,0,0);
            if (tok && (unsigned)h_in < HH && (unsigned)w_in < WWD)
                v = *(const uint4*)&g_y1h[(t_in*HWX + h_in*WWD + w_in)*64 + seg*8];
            *(uint4*)(WIN + pos*128 + ((seg ^ (pos&7))<<4)) = v;
        }
        #pragma unroll
        for (int j=0;j<9;j++){
            const uint4* sp = (const uint4*)(g_Woffh + (kt*9+j)*4096 + o_w*64 + part*16);
            uint4 v0 = sp[0], v1 = sp[1];
            char* SBj = SBc + j*8192;
            *(uint4*)(SBj + o_w*128 + ((s0w ^ (o_w&7))<<4)) = v0;
            *(uint4*)(SBj + o_w*128 + (((s0w+1)^(o_w&7))<<4)) = v1;
        }
        __syncthreads();
        #pragma unroll
        for (int j=0;j<9;j++){
            int kh = j/3, kw = j - kh*3;
            gemm_conv(WinB, whh + kh*66 + kw, Bb0 + j*8192, n0, lane, acc);
        }
    }
    __syncthreads();

    int q = lane>>2, c2 = (lane&3)<<1;
    // ---------- transition: offsets -> smem fp32 -> tap table ----------
    {
        float* sOut = (float*)(sm + 1024);   // [o][132]
        #pragma unroll
        for (int t8=0;t8<8;t8++){
            int mi=t8>>2, ni=(t8>>1)&1, hn=t8&1;
            int o = n0 + ni*16 + hn*8 + c2;
            int nn = m0 + mi*16 + q;
            float b0v = sBias[o], b1v = sBias[o+1];
            sOut[o*132+nn]       = acc[t8][0]+b0v;
            sOut[(o+1)*132+nn]   = acc[t8][1]+b1v;
            sOut[o*132+nn+8]     = acc[t8][2]+b0v;
            sOut[(o+1)*132+nn+8] = acc[t8][3]+b1v;
        }
        __syncthreads();
        for (int e = tid; e < KTAP*128; e += 256){
            int tap = e>>7, n = e&127;
            float dh = sOut[(2*tap)*132 + n];
            float dw = sOut[(2*tap+1)*132 + n];
            int hh = n>>6, w = n&63;
            int h = h0 + hh;
            int kt = tap/9, rr = tap-kt*9, kh = rr/3, kw = rr-kh*3;
            int t_in = t-1+kt;
            bool t_ok = (unsigned)t_in < TT;
            int t_c = min(max(t_in,0),TT-1);
            float h_s = (float)(h-1+kh)+dh, w_s = (float)(w-1+kw)+dw;
            float h0f = floorf(h_s), w0f = floorf(w_s);
            float fh = h_s-h0f, fw = w_s-w0f;
            int hb = (int)h0f, wb = (int)w0f;
            float wgt[4];
            unsigned short ofs[4];
            int tb = t_c*HWX;
            #pragma unroll
            for (int qq = 0; qq < 4; qq++){
                int ih = hb + (qq>>1), iw = wb + (qq&1);
                bool ok = t_ok && ((unsigned)ih < HH) && ((unsigned)iw < WWD);
                int ihc = min(max(ih,0),HH-1), iwc = min(max(iw,0),WWD-1);
                float whv = (qq>>1) ? fh : 1.f - fh;
                float wvv = (qq&1)  ? fw : 1.f - fw;
                wgt[qq] = ok ? whv*wvv : 0.f;
                ofs[qq] = (unsigned short)(tb + ihc*WWD + iwc);
            }
            __half2 w01 = __floats2half2_rn(wgt[0], wgt[1]);
            __half2 w23 = __floats2half2_rn(wgt[2], wgt[3]);
            sOff[e] = make_uint2((uint32_t)ofs[0] | ((uint32_t)ofs[1]<<16),
                                 (uint32_t)ofs[2] | ((uint32_t)ofs[3]<<16));
            uint2 wp; wp.x = *(uint32_t*)&w01; wp.y = *(uint32_t*)&w23;
            sWt[e] = wp;
        }
    }
    __syncthreads();

    // ---------- phase B: deformable GEMM + residual ----------
    #pragma unroll
    for (int i=0;i<8;i++){ acc[i][0]=0.f; acc[i][1]=0.f; acc[i][2]=0.f; acc[i][3]=0.f; }

    {
        uint4 P[2][4]; uint2 Wp[2];
        dledg(0, tid, sOff, sWt, P, Wp, 0); dlsts(SA0, tid, P, Wp, 0);
        dledg(0, tid, sOff, sWt, P, Wp, 2); dlsts(SA0, tid, P, Wp, 2);
        const uint4* sp = (const uint4*)(g_Wdh + o_w*64 + part*16);
        uint4 wv0 = sp[0], wv1 = sp[1];
        *(uint4*)(SB0 + o_w*128 + ((s0w ^ (o_w&7))<<4)) = wv0;
        *(uint4*)(SB0 + o_w*128 + (((s0w+1)^(o_w&7))<<4)) = wv1;
    }
    __syncthreads();

    for (int it = 0; it < 28; it++){
        int p = it & 1;
        uint32_t Ab = sbase + (p ? 17408 : 1024);
        uint32_t Bb = sbase + (p ? 41984 : 33792);
        char* SAn = p ? SA0 : SA1;
        char* SBn = p ? SB0 : SB1;
        int nxt = it + 1;
        bool more = nxt < 28;

        uint4 P[2][4]; uint2 Wp[2];
        uint4 wv0, wv1;
        if (more){
            if (nxt < 27) dledg(nxt, tid, sOff, sWt, P, Wp, 0);
            else          rledg(tid, base_p, P, Wp, 0);
            const __half* Wsrc = (nxt < 27) ? (g_Wdh + nxt*4096) : g_Wrh;
            const uint4* sp = (const uint4*)(Wsrc + o_w*64 + part*16);
            wv0 = sp[0]; wv1 = sp[1];
        }
        gemm_half<0>(Ab, Bb, m0, n0, lane, acc);
        if (more){
            dlsts(SAn, tid, P, Wp, 0);
            if (nxt < 27) dledg(nxt, tid, sOff, sWt, P, Wp, 2);
            else          rledg(tid, base_p, P, Wp, 2);
        }
        gemm_half<2>(Ab, Bb, m0, n0, lane, acc);
        if (more){
            dlsts(SAn, tid, P, Wp, 2);
            *(uint4*)(SBn + o_w*128 + ((s0w ^ (o_w&7))<<4)) = wv0;
            *(uint4*)(SBn + o_w*128 + (((s0w+1)^(o_w&7))<<4)) = wv1;
        }
        if (it == 26){
            #pragma unroll
            for (int t8=0;t8<8;t8++){
                int ni=(t8>>1)&1, hn=t8&1;
                int o = n0 + ni*16 + hn*8 + c2;
                float b0v = sBd[o], b1v = sBd[o+1];
                float v;
                v = acc[t8][0]+b0v; acc[t8][0] = v>=0.f?v:0.01f*v;
                v = acc[t8][1]+b1v; acc[t8][1] = v>=0.f?v:0.01f*v;
                v = acc[t8][2]+b0v; acc[t8][2] = v>=0.f?v:0.01f*v;
                v = acc[t8][3]+b1v; acc[t8][3] = v>=0.f?v:0.01f*v;
            }
        }
        __syncthreads();
    }

    float* sOut = (float*)(sm + 1024);  // [o][132]
    #pragma unroll
    for (int t8=0;t8<8;t8++){
        int mi=t8>>2, ni=(t8>>1)&1, hn=t8&1;
        int o = n0 + ni*16 + hn*8 + c2;
        int nn = m0 + mi*16 + q;
        float b0v = sBr[o], b1v = sBr[o+1];
        sOut[o*132+nn]       = acc[t8][0]+b0v;
        sOut[(o+1)*132+nn]   = acc[t8][1]+b1v;
        sOut[o*132+nn+8]     = acc[t8][2]+b0v;
        sOut[(o+1)*132+nn+8] = acc[t8][3]+b1v;
    }
    __syncthreads();
    int n4 = (tid&31)*4;
    #pragma unroll
    for (int i=0;i<8;i++){
        int o = (tid>>5) + i*8;
        float4 v = *(float4*)&sOut[o*132+n4];
        *(float4*)&out[o*PLANE + base_p + n4] = v;
    }
}

// -------- launch --------
extern "C" void kernel_launch(void* const* d_in, const int* in_sizes, int n_in,
                              void* d_out, int out_size) {
    (void)in_sizes; (void)n_in; (void)out_size;
    const float* x    = (const float*)d_in[0];
    const float* W1   = (const float*)d_in[1];
    const float* b1   = (const float*)d_in[2];
    const float* Woff = (const float*)d_in[3];
    const float* boff = (const float*)d_in[4];
    const float* Wd   = (const float*)d_in[5];
    const float* bd   = (const float*)d_in[6];
    const float* Wr   = (const float*)d_in[7];
    const float* br   = (const float*)d_in[8];
    float* out = (float*)d_out;

    cudaFuncSetAttribute(conv0_f16,  cudaFuncAttributeMaxDynamicSharedMemorySize, SMEM_CONV);
    cudaFuncSetAttribute(offdef_f16, cudaFuncAttributeMaxDynamicSharedMemorySize, SMEM_FUSED);

    prep_all<<<688, 256>>>(W1, Woff, Wd, Wr, x);
    conv0_f16<<<256, 256, SMEM_CONV>>>(b1);
    offdef_f16<<<256, 256, SMEM_FUSED>>>(boff, bd, br, out);
}